// round 16
// baseline (speedup 1.0000x reference)
#include <cuda_runtime.h>
#include <cuda_fp16.h>
#include <math.h>
#include <stdint.h>

#define D 128
#define MAXN 50176   // 50000 padded up to multiple of 128

__device__ __half g_Q[MAXN * D];
__device__ __half g_K[MAXN * D];
__device__ __half g_V[MAXN * D];
__device__ __half g_agg[MAXN * D];   // fp16 aggregation buffer

// fp16 smem tile stride (halves): 136 -> row stride 272B = 16 mod 128,
// so 8 consecutive rows hit 8 distinct 16B bank groups (ldmatrix conflict-free)
#define LDH 136
#define A_HALFS   (128 * LDH)
#define A64_HALFS (64 * LDH)
#define B64_HALFS (64 * LDH)
#define QKV_SMEM ((A_HALFS + B64_HALFS) * 2)    // 52224 B -> 4 CTAs/SM
#define OPJ_SMEM ((A64_HALFS + A_HALFS) * 2)    // 52224 B -> 4 CTAs/SM
// fp32 H-staging stride
#define LDT 132

#define SIGSCALE 0.08838834764831845f    // 1/sqrt(128)

// ---------------------------------------------------------------------------
// helpers
// ---------------------------------------------------------------------------
__device__ __forceinline__ uint32_t smem_u32(const void* p) {
    uint32_t a;
    asm("{ .reg .u64 t; cvta.to.shared.u64 t, %1; cvt.u32.u64 %0, t; }" : "=r"(a) : "l"(p));
    return a;
}

__device__ __forceinline__ void ldsm_x4(uint32_t r[4], uint32_t saddr) {
    asm volatile("ldmatrix.sync.aligned.m8n8.x4.shared.b16 {%0,%1,%2,%3}, [%4];"
                 : "=r"(r[0]), "=r"(r[1]), "=r"(r[2]), "=r"(r[3]) : "r"(saddr));
}

__device__ __forceinline__ void mma_f16(float d[4], const uint32_t a[4], const uint32_t b[2]) {
    asm volatile(
        "mma.sync.aligned.m16n8k16.row.col.f32.f16.f16.f32 "
        "{%0,%1,%2,%3}, {%4,%5,%6,%7}, {%8,%9}, {%0,%1,%2,%3};"
        : "+f"(d[0]), "+f"(d[1]), "+f"(d[2]), "+f"(d[3])
        : "r"(a[0]), "r"(a[1]), "r"(a[2]), "r"(a[3]), "r"(b[0]), "r"(b[1]));
}

// ---------------------------------------------------------------------------
// fp16 MMA main loop, 32x32 warp tile at (mb, nb).
// ---------------------------------------------------------------------------
__device__ __forceinline__ void mma_loop_f16(uint32_t a_smem, uint32_t b_smem,
                                             int mb, int nb, int lane,
                                             float acc[2][4][4])
{
    const int lr8 = lane & 7;
    const int q   = lane >> 3;

    uint32_t a_base[2], b_base[2];
#pragma unroll
    for (int i = 0; i < 2; ++i)
        a_base[i] = a_smem + (uint32_t)(((mb + i * 16 + (q & 1) * 8 + lr8) * LDH) * 2
                                        + (q >> 1) * 16);
#pragma unroll
    for (int p = 0; p < 2; ++p)
        b_base[p] = b_smem + (uint32_t)(((nb + p * 16 + (q >> 1) * 8 + lr8) * LDH) * 2
                                        + (q & 1) * 16);

#pragma unroll
    for (int i = 0; i < 2; ++i)
#pragma unroll
        for (int j = 0; j < 4; ++j)
#pragma unroll
            for (int t = 0; t < 4; ++t) acc[i][j][t] = 0.0f;

#pragma unroll
    for (int k0 = 0; k0 < 8; ++k0) {
        const uint32_t koff = k0 * 32;
        uint32_t A0[4], A1[4], B0[4], B1[4];
        ldsm_x4(A0, a_base[0] + koff);
        ldsm_x4(A1, a_base[1] + koff);
        ldsm_x4(B0, b_base[0] + koff);
        ldsm_x4(B1, b_base[1] + koff);

        mma_f16(acc[0][0], A0, &B0[0]);
        mma_f16(acc[0][1], A0, &B0[2]);
        mma_f16(acc[0][2], A0, &B1[0]);
        mma_f16(acc[0][3], A0, &B1[2]);
        mma_f16(acc[1][0], A1, &B0[0]);
        mma_f16(acc[1][1], A1, &B0[2]);
        mma_f16(acc[1][2], A1, &B1[0]);
        mma_f16(acc[1][3], A1, &B1[2]);
    }
}

__device__ __forceinline__ uint2 f4_to_h4(float4 f) {
    __half2 h0 = __floats2half2_rn(f.x, f.y);
    __half2 h1 = __floats2half2_rn(f.z, f.w);
    uint2 u;
    u.x = *(uint32_t*)&h0;
    u.y = *(uint32_t*)&h1;
    return u;
}

// ---------------------------------------------------------------------------
// QKV kernel, A-reuse: grid (mb, 2). Each CTA loads the X tile ONCE and
// loops over the 3 weights (col half c0). 256 threads, 52KB -> 4 CTAs/SM.
// ---------------------------------------------------------------------------
__global__ void __launch_bounds__(256, 4)
qkv_kernel(const float* __restrict__ X,
           const float* __restrict__ Wq, const float* __restrict__ Wk,
           const float* __restrict__ Wv,
           __half* __restrict__ Q, __half* __restrict__ K, __half* __restrict__ V,
           int N)
{
    extern __shared__ __half hsm[];
    __half* Ah = hsm;
    __half* Bh = hsm + A_HALFS;

    const int tid = threadIdx.x;
    const int m0 = blockIdx.x * 128;
    const int c0 = blockIdx.y * 64;

    const float* Wlist[3] = {Wq, Wk, Wv};
    __half*      Olist[3] = {Q, K, V};

    // A tile: 128 rows x 32 float4 -> fp16, 16 per thread (loaded ONCE)
#pragma unroll
    for (int i = 0; i < 16; ++i) {
        int idx = tid + i * 256;
        int m = idx >> 5;
        int c = idx & 31;
        int gm = m0 + m;
        float4 f = (gm < N) ? *(const float4*)(X + (size_t)gm * D + c * 4)
                            : make_float4(0.f, 0.f, 0.f, 0.f);
        *(uint2*)(Ah + m * LDH + c * 4) = f4_to_h4(f);
    }

    const int lane = tid & 31;
    const int warp = tid >> 5;
    const int mb = (warp & 3) * 32;
    const int nb = (warp >> 2) * 32;
    const int lq = lane >> 2;
    const int lr = lane & 3;

#pragma unroll
    for (int w = 0; w < 3; ++w) {
        // load B tile: 64 rows (c0..c0+63 of W_w), 8 float4 per thread
        const float* W = Wlist[w];
#pragma unroll
        for (int i = 0; i < 8; ++i) {
            int idx = tid + i * 256;
            int r = idx >> 5;
            int c = idx & 31;
            float4 f = *(const float4*)(W + (size_t)(c0 + r) * D + c * 4);
            *(uint2*)(Bh + r * LDH + c * 4) = f4_to_h4(f);
        }
        __syncthreads();   // B (and A on first iter) ready

        float acc[2][4][4];
        mma_loop_f16(smem_u32(Ah), smem_u32(Bh), mb, nb, lane, acc);

        __half* O = Olist[w];
#pragma unroll
        for (int i = 0; i < 2; ++i) {
            int row = m0 + mb + i * 16 + lq;
#pragma unroll
            for (int j = 0; j < 4; ++j) {
                int col = c0 + nb + j * 8 + lr * 2;
                if (row < N)
                    *(__half2*)(O + (size_t)row * D + col) =
                        __floats2half2_rn(acc[i][j][0], acc[i][j][1]);
                if (row + 8 < N)
                    *(__half2*)(O + (size_t)(row + 8) * D + col) =
                        __floats2half2_rn(acc[i][j][2], acc[i][j][3]);
            }
        }
        __syncthreads();   // all warps done reading Bh before next fill
    }
}

// ---------------------------------------------------------------------------
// O-proj + bias + residual + LayerNorm fused. M-split: 64x128 tile per CTA,
// 256 threads, 52KB smem -> 4 CTAs/SM. LN keeps full 128-wide rows.
// ---------------------------------------------------------------------------
__global__ void __launch_bounds__(256, 4)
oproj_ln_kernel(const __half* __restrict__ AGG, const float* __restrict__ Wo,
                const float* __restrict__ X,
                const float* __restrict__ bo, const float* __restrict__ gamma,
                const float* __restrict__ beta,
                float* __restrict__ out, int N)
{
    extern __shared__ __half hsm[];
    __half* Ah = hsm;                    // 64 x LDH fp16
    __half* Bh = hsm + A64_HALFS;        // 128 x LDH fp16 (Wo)
    float* Hs = (float*)hsm;             // 64 x LDT fp32 staging (aliases)
    __shared__ float P[384];

    const int tid = threadIdx.x;
    if (tid < 128)      P[tid]       = bo[tid];
    else                P[tid]       = gamma[tid - 128];
    if (tid < 128)      P[256 + tid] = beta[tid];

    const int m0 = blockIdx.x * 64;

    // A tile: 64 rows x 16 uint4 (fp16 direct copy), 4 per thread
#pragma unroll
    for (int i = 0; i < 4; ++i) {
        int idx = tid + i * 256;
        int m = idx >> 4;
        int c = idx & 15;
        int gm = m0 + m;
        uint4 v = (gm < N) ? *(const uint4*)(AGG + (size_t)gm * D + c * 8)
                           : make_uint4(0u, 0u, 0u, 0u);
        *(uint4*)(Ah + m * LDH + c * 8) = v;
    }
    // B tile: full Wo 128 rows fp32 -> fp16, 16 per thread
#pragma unroll
    for (int i = 0; i < 16; ++i) {
        int idx = tid + i * 256;
        int m = idx >> 5;
        int c = idx & 31;
        float4 g = *(const float4*)(Wo + (size_t)m * D + c * 4);
        *(uint2*)(Bh + m * LDH + c * 4) = f4_to_h4(g);
    }
    __syncthreads();

    const int lane = tid & 31;
    const int warp = tid >> 5;
    const int mb = (warp & 1) * 32;
    const int nb = (warp >> 1) * 32;

    float acc[2][4][4];
    mma_loop_f16(smem_u32(Ah), smem_u32(Bh), mb, nb, lane, acc);
    __syncthreads();

    const int lq = lane >> 2;
    const int lr = lane & 3;

#pragma unroll
    for (int i = 0; i < 2; ++i) {
        int r = mb + i * 16 + lq;
#pragma unroll
        for (int j = 0; j < 4; ++j) {
            int c = nb + j * 8 + lr * 2;
            *(float2*)(Hs + r * LDT + c)       = make_float2(acc[i][j][0], acc[i][j][1]);
            *(float2*)(Hs + (r + 8) * LDT + c) = make_float2(acc[i][j][2], acc[i][j][3]);
        }
    }
    __syncthreads();

#pragma unroll
    for (int p = 0; p < 8; ++p) {
        int r = warp * 8 + p;
        int grow = m0 + r;
        if (grow >= N) continue;

        float4 h = *(float4*)(Hs + r * LDT + lane * 4);
        float4 xb = *(const float4*)(X + (size_t)grow * D + lane * 4);
        float4 bb = *(const float4*)(P + lane * 4);
        h.x += xb.x + bb.x; h.y += xb.y + bb.y;
        h.z += xb.z + bb.z; h.w += xb.w + bb.w;

        float s  = h.x + h.y + h.z + h.w;
        float s2 = h.x * h.x + h.y * h.y + h.z * h.z + h.w * h.w;
#pragma unroll
        for (int o = 16; o; o >>= 1) {
            s  += __shfl_xor_sync(0xffffffffu, s,  o);
            s2 += __shfl_xor_sync(0xffffffffu, s2, o);
        }
        float mu  = s * (1.0f / 128.0f);
        float var = s2 * (1.0f / 128.0f) - mu * mu;
        float rv  = rsqrtf(var + 1e-5f);

        float4 gm = *(const float4*)(P + 128 + lane * 4);
        float4 bt = *(const float4*)(P + 256 + lane * 4);
        float4 o;
        o.x = (h.x - mu) * rv * gm.x + bt.x;
        o.y = (h.y - mu) * rv * gm.y + bt.y;
        o.z = (h.z - mu) * rv * gm.z + bt.z;
        o.w = (h.w - mu) * rv * gm.w + bt.w;
        *(float4*)(out + (size_t)grow * D + lane * 4) = o;
    }
}

// ---------------------------------------------------------------------------
// zero kernel (uint4 over fp16 agg)
// ---------------------------------------------------------------------------
__global__ void zero_kernel(uint4* __restrict__ p, int n16) {
    int i = blockIdx.x * blockDim.x + threadIdx.x;
    if (i < n16) p[i] = make_uint4(0u, 0u, 0u, 0u);
}

// ---------------------------------------------------------------------------
// Edge kernel: TWO edges per warp, 16 lanes each (full-warp utilization).
// ---------------------------------------------------------------------------
__global__ void edge_kernel(const int* __restrict__ ei,
                            const __half* __restrict__ Q,
                            const __half* __restrict__ K,
                            const __half* __restrict__ V,
                            __half* __restrict__ agg,
                            int E)
{
    int gwarp = (blockIdx.x * blockDim.x + threadIdx.x) >> 5;
    int lane  = threadIdx.x & 31;
    int half  = lane >> 4;
    int l16   = lane & 15;

    int ew = gwarp * 2 + half;
    bool valid = (ew < E);
    int ewc = valid ? ew : (E - 1);

    int src = ei[ewc];
    int dst = ei[E + ewc];

    uint4 qu = *(const uint4*)(Q + (size_t)dst * D + l16 * 8);
    uint4 ku = *(const uint4*)(K + (size_t)src * D + l16 * 8);

    float d = 0.f;
#pragma unroll
    for (int t = 0; t < 4; ++t) {
        float2 qf = __half22float2(*((const __half2*)&qu + t));
        float2 kf = __half22float2(*((const __half2*)&ku + t));
        d += qf.x * kf.x + qf.y * kf.y;
    }
#pragma unroll
    for (int o = 8; o; o >>= 1) d += __shfl_xor_sync(0xffffffffu, d, o);

    float s = 1.0f / (1.0f + __expf(-d * SIGSCALE));
    __half2 s2 = __float2half2_rn(s);

    uint4 vu = *(const uint4*)(V + (size_t)src * D + l16 * 8);
    __half2 m0 = __hmul2(*(__half2*)&vu.x, s2);
    __half2 m1 = __hmul2(*(__half2*)&vu.y, s2);
    __half2 m2 = __hmul2(*(__half2*)&vu.z, s2);
    __half2 m3 = __hmul2(*(__half2*)&vu.w, s2);

    if (valid) {
        __half* p = agg + (size_t)dst * D + l16 * 8;
        asm volatile(
            "red.global.add.noftz.v4.f16x2 [%0], {%1, %2, %3, %4};"
            :: "l"(p),
               "r"(*(uint32_t*)&m0), "r"(*(uint32_t*)&m1),
               "r"(*(uint32_t*)&m2), "r"(*(uint32_t*)&m3)
            : "memory");
    }
}

// ---------------------------------------------------------------------------
// launch
// ---------------------------------------------------------------------------
extern "C" void kernel_launch(void* const* d_in, const int* in_sizes, int n_in,
                              void* d_out, int out_size)
{
    const float* x     = (const float*)d_in[0];
    const int*   ei    = (const int*)  d_in[1];
    const float* Wq    = (const float*)d_in[2];
    const float* Wk    = (const float*)d_in[3];
    const float* Wv    = (const float*)d_in[4];
    const float* Wo    = (const float*)d_in[5];
    const float* bo    = (const float*)d_in[6];
    const float* gamma = (const float*)d_in[7];
    const float* beta  = (const float*)d_in[8];
    float*       out   = (float*)d_out;

    const int N = in_sizes[0] / D;
    const int E = in_sizes[1] / 2;

    __half *Q, *K, *V, *agg;
    cudaGetSymbolAddress((void**)&Q,   g_Q);
    cudaGetSymbolAddress((void**)&K,   g_K);
    cudaGetSymbolAddress((void**)&V,   g_V);
    cudaGetSymbolAddress((void**)&agg, g_agg);

    cudaFuncSetAttribute(qkv_kernel, cudaFuncAttributeMaxDynamicSharedMemorySize, QKV_SMEM);
    cudaFuncSetAttribute(oproj_ln_kernel, cudaFuncAttributeMaxDynamicSharedMemorySize, OPJ_SMEM);

    const int mb = (N + 127) / 128;
    const int mb64 = (N + 63) / 64;
    const int n16 = N * D / 8;
    const int ewarps = (E + 1) / 2;

    zero_kernel<<<(n16 + 255) / 256, 256>>>((uint4*)agg, n16);

    qkv_kernel<<<dim3(mb, 2), 256, QKV_SMEM>>>(x, Wq, Wk, Wv, Q, K, V, N);

    edge_kernel<<<(ewarps + 7) / 8, 256>>>(ei, Q, K, V, agg, E);

    oproj_ln_kernel<<<mb64, 256, OPJ_SMEM>>>(agg, Wo, x, bo, gamma, beta, out, N);
}